// round 15
// baseline (speedup 1.0000x reference)
#include <cuda_runtime.h>
#include <cuda_fp16.h>
#include <math.h>
#include <stdint.h>

#define NTOK 4096
#define DMODEL 320
#define FFI 1280
#define HEADS 8
#define DH 40
#define CTXN 77
#define CTXD 768
#define CTXP 128
#define QSCALE (0.15811388300841897f * 1.4426950408889634f)  // dh^-0.5 * log2(e)

// ---------------- scratch ----------------
__device__ float g_s[DMODEL];
__device__ float g_t[DMODEL];
__device__ float g_bp[DMODEL];
__device__ float g_h[NTOK * DMODEL];
__device__ float g_bff1[2 * FFI];

// fp16 activations
__device__ __align__(16) __half g_x16[NTOK * DMODEL];
__device__ __align__(16) __half g_ln16[NTOK * DMODEL];
__device__ __align__(16) __half g_qk16[NTOK * 2 * DMODEL];
__device__ __align__(16) __half g_vt16[DMODEL * NTOK];
__device__ __align__(16) __half g_q216[NTOK * DMODEL];
__device__ __align__(16) __half g_k216[CTXN * DMODEL];
__device__ __align__(16) __half g_vt2c16[DMODEL * CTXP];
__device__ __align__(16) __half g_ao16[NTOK * DMODEL];
__device__ __align__(16) __half g_fa16[NTOK * FFI];
__device__ __align__(16) __half g_hh16[NTOK * DMODEL];
__device__ __align__(16) __half g_ctx16[CTXN * CTXD];
// fp16 weights, [N][K]
__device__ __align__(16) __half g_wpin16[DMODEL * DMODEL];
__device__ __align__(16) __half g_wqkv16[3 * DMODEL * DMODEL];  // q(scaled)|k|v
__device__ __align__(16) __half g_wq216[DMODEL * DMODEL];
__device__ __align__(16) __half g_wkv216[2 * DMODEL * CTXD];    // k2|v2
__device__ __align__(16) __half g_wo116[DMODEL * DMODEL];
__device__ __align__(16) __half g_wo216[DMODEL * DMODEL];
__device__ __align__(16) __half g_wff116[2 * FFI * DMODEL];
__device__ __align__(16) __half g_wff216[DMODEL * FFI];
__device__ __align__(16) __half g_wpo16[DMODEL * DMODEL];

// ---------------- helpers ----------------
__device__ __forceinline__ uint32_t smem_u32(const void* p) {
    return (uint32_t)__cvta_generic_to_shared(p);
}
__device__ __forceinline__ void cp16(uint32_t dst, const void* src, bool pred) {
    int sz = pred ? 16 : 0;
    asm volatile("cp.async.cg.shared.global [%0], [%1], 16, %2;" :: "r"(dst), "l"(src), "r"(sz));
}
__device__ __forceinline__ void cp_commit() { asm volatile("cp.async.commit_group;"); }
__device__ __forceinline__ void cp_wait1() { asm volatile("cp.async.wait_group 1;"); }

__device__ __forceinline__ void mma_f16(float* d, const uint32_t* a, uint32_t b0, uint32_t b1) {
    asm volatile(
        "mma.sync.aligned.m16n8k16.row.col.f32.f16.f16.f32 "
        "{%0,%1,%2,%3}, {%4,%5,%6,%7}, {%8,%9}, {%0,%1,%2,%3};"
        : "+f"(d[0]), "+f"(d[1]), "+f"(d[2]), "+f"(d[3])
        : "r"(a[0]), "r"(a[1]), "r"(a[2]), "r"(a[3]), "r"(b0), "r"(b1));
}
__device__ __forceinline__ float gelu_f(float g) {
    return 0.5f * g * (1.f + erff(g * 0.70710678118654752f));
}
__device__ __forceinline__ uint32_t packh2(float a, float b) {
    __half2 p = __floats2half2_rn(a, b);
    return *(uint32_t*)&p;
}

// ---------------- GroupNorm stats ----------------
__global__ void gn_stats_kernel(const float* __restrict__ x,
                                const float* __restrict__ gn_w,
                                const float* __restrict__ gn_b) {
    int g = blockIdx.x;
    int tid = threadIdx.x;
    const float* base = x + (size_t)g * 10 * 4096;
    float s = 0.f, ss = 0.f;
    for (int i = tid; i < 40960; i += 256) {
        float v = base[i];
        s += v; ss += v * v;
    }
    __shared__ float r1[256], r2[256];
    r1[tid] = s; r2[tid] = ss;
    __syncthreads();
    for (int off = 128; off > 0; off >>= 1) {
        if (tid < off) { r1[tid] += r1[tid + off]; r2[tid] += r2[tid + off]; }
        __syncthreads();
    }
    if (tid < 10) {
        float mu = r1[0] / 40960.f;
        float var = r2[0] / 40960.f - mu * mu;
        float inv = rsqrtf(var + 1e-6f);
        int c = g * 10 + tid;
        float w = gn_w[c];
        g_s[c] = inv * w;
        g_t[c] = gn_b[c] - mu * inv * w;
    }
}

__global__ void fold_pin_kernel(const float* __restrict__ pin_w,
                                const float* __restrict__ pin_b) {
    int o = blockIdx.x;
    int tid = threadIdx.x;
    float acc = 0.f;
    for (int c = tid; c < DMODEL; c += 64) {
        float w = pin_w[o * DMODEL + c];
        g_wpin16[o * DMODEL + c] = __float2half(w * g_s[c]);
        acc += w * g_t[c];
    }
    __shared__ float r[64];
    r[tid] = acc;
    __syncthreads();
    for (int off = 32; off > 0; off >>= 1) {
        if (tid < off) r[tid] += r[tid + off];
        __syncthreads();
    }
    if (tid == 0) g_bp[o] = pin_b[o] + r[0];
}

// ---------------- unified weight prep ----------------
__device__ __forceinline__ void tr_tile(const float* __restrict__ in, __half* __restrict__ out,
                                        int R, int Cc, int bx, int by, float scale) {
    __shared__ float tile[32][33];
    int tx = threadIdx.x & 31, ty = threadIdx.x >> 5;
    int c0 = bx * 32, r0 = by * 32;
#pragma unroll
    for (int i = 0; i < 4; i++) {
        int r = r0 + ty + i * 8, c = c0 + tx;
        if (r < R && c < Cc) tile[ty + i * 8][tx] = in[(size_t)r * Cc + c];
    }
    __syncthreads();
#pragma unroll
    for (int i = 0; i < 4; i++) {
        int c = c0 + ty + i * 8, r = r0 + tx;
        if (c < Cc && r < R) out[(size_t)c * R + r] = __float2half(tile[tx][ty + i * 8] * scale);
    }
}

#define PREP_BLOCKS 3728
__global__ __launch_bounds__(256) void prep_kernel(
    const float* __restrict__ x,
    const float* __restrict__ q1, const float* __restrict__ k1,
    const float* __restrict__ v1, const float* __restrict__ o1w,
    const float* __restrict__ q2, const float* __restrict__ k2,
    const float* __restrict__ v2, const float* __restrict__ o2w,
    const float* __restrict__ ff1w, const float* __restrict__ ff1b,
    const float* __restrict__ ff2w, const float* __restrict__ poutw,
    const float* __restrict__ ctx) {
    int b = blockIdx.x;
    int tid = threadIdx.x;
    if (b < 1280) { tr_tile(x, g_x16, DMODEL, NTOK, b % 128, b / 128, 1.f); return; }
    b -= 1280;
    if (b < 100) { tr_tile(q1, g_wqkv16, DMODEL, DMODEL, b % 10, b / 10, QSCALE); return; }
    b -= 100;
    if (b < 100) { tr_tile(k1, g_wqkv16 + DMODEL * DMODEL, DMODEL, DMODEL, b % 10, b / 10, 1.f); return; }
    b -= 100;
    if (b < 100) { tr_tile(v1, g_wqkv16 + 2 * DMODEL * DMODEL, DMODEL, DMODEL, b % 10, b / 10, 1.f); return; }
    b -= 100;
    if (b < 100) { tr_tile(o1w, g_wo116, DMODEL, DMODEL, b % 10, b / 10, 1.f); return; }
    b -= 100;
    if (b < 100) { tr_tile(q2, g_wq216, DMODEL, DMODEL, b % 10, b / 10, QSCALE); return; }
    b -= 100;
    if (b < 240) { tr_tile(k2, g_wkv216, CTXD, DMODEL, b % 10, b / 10, 1.f); return; }
    b -= 240;
    if (b < 240) { tr_tile(v2, g_wkv216 + DMODEL * CTXD, CTXD, DMODEL, b % 10, b / 10, 1.f); return; }
    b -= 240;
    if (b < 100) { tr_tile(o2w, g_wo216, DMODEL, DMODEL, b % 10, b / 10, 1.f); return; }
    b -= 100;
    if (b < 400) { tr_tile(ff2w, g_wff216, FFI, DMODEL, b % 10, b / 10, 1.f); return; }
    b -= 400;
    if (b < 800) {
        __shared__ float tile[32][33];
        int tx = tid & 31, ty = tid >> 5;
        int bx = b % 80, by = b / 80;
        int c0 = bx * 32, r0 = by * 32;
#pragma unroll
        for (int i = 0; i < 4; i++) {
            int k = r0 + ty + i * 8, n = c0 + tx;
            int src = (n & 1) ? (FFI + (n >> 1)) : (n >> 1);
            tile[ty + i * 8][tx] = ff1w[(size_t)k * 2 * FFI + src];
        }
        __syncthreads();
#pragma unroll
        for (int i = 0; i < 4; i++) {
            int n = c0 + ty + i * 8, k = r0 + tx;
            g_wff116[(size_t)n * DMODEL + k] = __float2half(tile[tx][ty + i * 8]);
        }
        return;
    }
    b -= 800;
    if (b < 100) {
        int i0 = b * 1024 + tid * 4;
#pragma unroll
        for (int i = 0; i < 4; i++) g_wpo16[i0 + i] = __float2half(poutw[i0 + i]);
        return;
    }
    b -= 100;
    if (b < 58) {
        int i0 = b * 1024 + tid * 4;
#pragma unroll
        for (int i = 0; i < 4; i++) {
            int idx = i0 + i;
            if (idx < CTXN * CTXD) g_ctx16[idx] = __float2half(ctx[idx]);
        }
        return;
    }
    b -= 58;
    int idx = b * 256 + tid;
    int j = idx >> 1;
    g_bff1[idx] = (idx & 1) ? ff1b[FFI + j] : ff1b[j];
}

// ---------------- fp16 tensor-core GEMM, 64x64 tile, BK=32, 3-stage ----------------
__global__ __launch_bounds__(128) void gemm_fp16(
    const __half* __restrict__ A, const __half* __restrict__ B,
    float* __restrict__ C, __half* __restrict__ Ch, __half* __restrict__ Ch2,
    const float* __restrict__ bias, const float* __restrict__ resid,
    int M, int N, int K, int Csm, int Csn, int mode, int split, int ld2) {
    __shared__ __align__(16) uint32_t As[3][64][20];
    __shared__ __align__(16) uint32_t Bs[3][64][20];
    int tid = threadIdx.x;
    int warp = tid >> 5, lane = tid & 31;
    int grp = lane >> 2, t4 = lane & 3;
    int m0 = blockIdx.x * 64, n0 = blockIdx.y * 64;
    int wm = (warp >> 1) * 32, wn = (warp & 1) * 32;

    float acc[2][4][4];
#pragma unroll
    for (int mi = 0; mi < 2; mi++)
#pragma unroll
        for (int ni = 0; ni < 4; ni++)
#pragma unroll
            for (int r = 0; r < 4; r++) acc[mi][ni][r] = 0.f;

    int r0s = tid >> 2, c0s = tid & 3;
    int r1s = (tid + 128) >> 2, c1s = tid & 3;
    bool ap0 = (m0 + r0s) < M, ap1 = (m0 + r1s) < M;
    const __half* a0 = A + (size_t)(ap0 ? (m0 + r0s) : 0) * K + c0s * 8;
    const __half* a1 = A + (size_t)(ap1 ? (m0 + r1s) : 0) * K + c1s * 8;
    const __half* b0 = B + (size_t)(n0 + r0s) * K + c0s * 8;
    const __half* b1 = B + (size_t)(n0 + r1s) * K + c1s * 8;

    auto prefetch = [&](int st, int k0) {
        cp16(smem_u32(&As[st][r0s][c0s * 4]), a0 + k0, ap0);
        cp16(smem_u32(&As[st][r1s][c1s * 4]), a1 + k0, ap1);
        cp16(smem_u32(&Bs[st][r0s][c0s * 4]), b0 + k0, true);
        cp16(smem_u32(&Bs[st][r1s][c1s * 4]), b1 + k0, true);
    };

    int nK = K >> 5;
    prefetch(0, 0);
    cp_commit();
    if (nK > 1) prefetch(1, 32);
    cp_commit();
    int st = 0;
    for (int kt = 0; kt < nK; kt++) {
        cp_wait1();
        __syncthreads();
        int pf = kt + 2;
        if (pf < nK) prefetch(pf % 3, pf << 5);
        cp_commit();
#pragma unroll
        for (int kk = 0; kk < 2; kk++) {
            uint32_t af[2][4];
#pragma unroll
            for (int mi = 0; mi < 2; mi++) {
                int rm = wm + mi * 16;
                af[mi][0] = As[st][rm + grp][kk * 8 + t4];
                af[mi][1] = As[st][rm + grp + 8][kk * 8 + t4];
                af[mi][2] = As[st][rm + grp][kk * 8 + 4 + t4];
                af[mi][3] = As[st][rm + grp + 8][kk * 8 + 4 + t4];
            }
            uint32_t bf[4][2];
#pragma unroll
            for (int ni = 0; ni < 4; ni++) {
                int cn = wn + ni * 8 + grp;
                bf[ni][0] = Bs[st][cn][kk * 8 + t4];
                bf[ni][1] = Bs[st][cn][kk * 8 + 4 + t4];
            }
#pragma unroll
            for (int mi = 0; mi < 2; mi++)
#pragma unroll
                for (int ni = 0; ni < 4; ni++)
                    mma_f16(acc[mi][ni], af[mi], bf[ni][0], bf[ni][1]);
        }
        st = (st == 2) ? 0 : st + 1;
    }
#pragma unroll
    for (int mi = 0; mi < 2; mi++) {
        int r0r = m0 + wm + mi * 16 + grp;
        int r1r = r0r + 8;
#pragma unroll
        for (int ni = 0; ni < 4; ni++) {
            int c = n0 + wn + ni * 8 + t4 * 2;
            float b0v = bias ? bias[c] : 0.f;
            float b1v = bias ? bias[c + 1] : 0.f;
            if (mode == 1) {
                int co = c >> 1;
                if (r0r < M)
                    Ch[(size_t)r0r * Csm + co] =
                        __float2half((acc[mi][ni][0] + b0v) * gelu_f(acc[mi][ni][1] + b1v));
                if (r1r < M)
                    Ch[(size_t)r1r * Csm + co] =
                        __float2half((acc[mi][ni][2] + b0v) * gelu_f(acc[mi][ni][3] + b1v));
            } else if (mode == 2) {
                if (c < split) {
                    if (r0r < M) {
                        Ch[(size_t)r0r * Csm + c]     = __float2half(acc[mi][ni][0]);
                        Ch[(size_t)r0r * Csm + c + 1] = __float2half(acc[mi][ni][1]);
                    }
                    if (r1r < M) {
                        Ch[(size_t)r1r * Csm + c]     = __float2half(acc[mi][ni][2]);
                        Ch[(size_t)r1r * Csm + c + 1] = __float2half(acc[mi][ni][3]);
                    }
                } else {
                    int ct = c - split;
                    if (r0r < M) {
                        Ch2[(size_t)ct * ld2 + r0r]       = __float2half(acc[mi][ni][0]);
                        Ch2[(size_t)(ct + 1) * ld2 + r0r] = __float2half(acc[mi][ni][1]);
                    }
                    if (r1r < M) {
                        Ch2[(size_t)ct * ld2 + r1r]       = __float2half(acc[mi][ni][2]);
                        Ch2[(size_t)(ct + 1) * ld2 + r1r] = __float2half(acc[mi][ni][3]);
                    }
                }
            } else {
                if (r0r < M) {
                    size_t o0 = (size_t)r0r * Csm + (size_t)c * Csn;
                    size_t o1 = o0 + Csn;
                    float v0 = acc[mi][ni][0] + b0v;
                    float v1 = acc[mi][ni][1] + b1v;
                    if (resid) { v0 += resid[o0]; v1 += resid[o1]; }
                    if (C) { C[o0] = v0; C[o1] = v1; }
                    if (Ch) { Ch[o0] = __float2half(v0); Ch[o1] = __float2half(v1); }
                }
                if (r1r < M) {
                    size_t o0 = (size_t)r1r * Csm + (size_t)c * Csn;
                    size_t o1 = o0 + Csn;
                    float v0 = acc[mi][ni][2] + b0v;
                    float v1 = acc[mi][ni][3] + b1v;
                    if (resid) { v0 += resid[o0]; v1 += resid[o1]; }
                    if (C) { C[o0] = v0; C[o1] = v1; }
                    if (Ch) { Ch[o0] = __float2half(v0); Ch[o1] = __float2half(v1); }
                }
            }
        }
    }
}

// ---------------- LayerNorm ----------------
__global__ __launch_bounds__(256) void ln_kernel(const float* __restrict__ in,
                                                 const float* __restrict__ w,
                                                 const float* __restrict__ b,
                                                 __half* __restrict__ out) {
    int warp = threadIdx.x >> 5, lane = threadIdx.x & 31;
    int m = blockIdx.x * 8 + warp;
    const float* row = in + (size_t)m * DMODEL;
    float vals[10];
    float s = 0.f, ss = 0.f;
#pragma unroll
    for (int i = 0; i < 10; i++) {
        float v = row[lane + i * 32];
        vals[i] = v;
        s += v; ss += v * v;
    }
#pragma unroll
    for (int off = 16; off > 0; off >>= 1) {
        s += __shfl_xor_sync(0xffffffffu, s, off);
        ss += __shfl_xor_sync(0xffffffffu, ss, off);
    }
    float mu = s / (float)DMODEL;
    float var = ss / (float)DMODEL - mu * mu;
    float rs = rsqrtf(var + 1e-5f);
#pragma unroll
    for (int i = 0; i < 10; i++) {
        int c = lane + i * 32;
        out[(size_t)m * DMODEL + c] = __float2half((vals[i] - mu) * rs * w[c] + b[c]);
    }
}

// ---------------- fp16 flash attention: 3-stage pipeline, exp2 softmax ----------------
__global__ __launch_bounds__(256) void attn16(
    const __half* __restrict__ Q, int ldq,
    const __half* __restrict__ K, int ldk,
    const __half* __restrict__ Vt, int ldv,
    __half* __restrict__ O, int n_k) {
    __shared__ __align__(16) uint32_t Ks[3][64][20];
    __shared__ __align__(16) uint32_t Vs[3][40][36];

    int h = blockIdx.y;
    int m0 = blockIdx.x * 128;
    int tid = threadIdx.x;
    int warp = tid >> 5, lane = tid & 31;
    int grp = lane >> 2, t4 = lane & 3;
    int wm = warp * 16;
    int row0 = m0 + wm + grp, row1 = row0 + 8;

    uint32_t qf[3][4];
#pragma unroll
    for (int kt = 0; kt < 3; kt++) {
        int d0 = h * DH + kt * 16 + 2 * t4;
        qf[kt][0] = *(const uint32_t*)(Q + (size_t)row0 * ldq + d0);
        qf[kt][1] = *(const uint32_t*)(Q + (size_t)row1 * ldq + d0);
        if (kt < 2) {
            qf[kt][2] = *(const uint32_t*)(Q + (size_t)row0 * ldq + d0 + 8);
            qf[kt][3] = *(const uint32_t*)(Q + (size_t)row1 * ldq + d0 + 8);
        } else {
            qf[kt][2] = 0; qf[kt][3] = 0;
        }
    }

    float o[5][4];
#pragma unroll
    for (int d = 0; d < 5; d++)
#pragma unroll
        for (int r = 0; r < 4; r++) o[d][r] = 0.f;
    float m_r0 = -1e30f, m_r1 = -1e30f, l_r0 = 0.f, l_r1 = 0.f;

    auto prefetch = [&](int st, int kt0) {
        for (int t = tid; t < 320; t += 256) {
            int r = t / 5, ch = t - r * 5;
            bool pred = (kt0 + r) < n_k;
            const __half* src = K + (size_t)(pred ? (kt0 + r) : 0) * ldk + h * DH + ch * 8;
            cp16(smem_u32(&Ks[st][r][ch * 4]), src, pred);
        }
        if (tid < 160) {
            int r = tid >> 2, ch = tid & 3;
            const __half* src = Vt + (size_t)(h * DH + r) * ldv + kt0 + ch * 16;
            cp16(smem_u32(&Vs[st][r][ch * 8]), src, true);
            src += 8;
            cp16(smem_u32(&Vs[st][r][ch * 8 + 4]), src, true);
        }
    };

    int nT = (n_k + 63) >> 6;
    prefetch(0, 0);
    cp_commit();
    if (nT > 1) prefetch(1, 64);
    cp_commit();
    int st = 0;
    for (int it = 0; it < nT; it++) {
        cp_wait1();
        __syncthreads();
        int pf = it + 2;
        if (pf < nT) prefetch(pf % 3, pf * 64);
        cp_commit();
        int kcount = min(64, n_k - it * 64);

        float s[8][4];
#pragma unroll
        for (int nt = 0; nt < 8; nt++)
#pragma unroll
            for (int r = 0; r < 4; r++) s[nt][r] = 0.f;
#pragma unroll
        for (int kt = 0; kt < 3; kt++) {
#pragma unroll
            for (int nt = 0; nt < 8; nt++) {
                int kr = nt * 8 + grp;
                uint32_t b0 = Ks[st][kr][kt * 8 + t4];
                uint32_t b1 = (kt < 2) ? Ks[st][kr][kt * 8 + 4 + t4] : 0u;
                mma_f16(s[nt], qf[kt], b0, b1);
            }
        }
        if (kcount < 64) {
#pragma unroll
            for (int nt = 0; nt < 8; nt++) {
                int c0 = nt * 8 + 2 * t4;
                if (c0 >= kcount)     { s[nt][0] = -1e30f; s[nt][2] = -1e30f; }
                if (c0 + 1 >= kcount) { s[nt][1] = -1e30f; s[nt][3] = -1e30f; }
            }
        }

        float mx0 = m_r0, mx1 = m_r1;
#pragma unroll
        for (int nt = 0; nt < 8; nt++) {
            mx0 = fmaxf(mx0, fmaxf(s[nt][0], s[nt][1]));
            mx1 = fmaxf(mx1, fmaxf(s[nt][2], s[nt][3]));
        }
        mx0 = fmaxf(mx0, __shfl_xor_sync(0xffffffffu, mx0, 1));
        mx0 = fmaxf(mx0, __shfl_xor_sync(0xffffffffu, mx0, 2));
        mx1 = fmaxf(mx1, __shfl_xor_sync(0xffffffffu, mx1, 1));
        mx1 = fmaxf(mx1, __shfl_xor_sync(0xffffffffu, mx1, 2));
        float f0 = exp2f(m_r0 - mx0), f1 = exp2f(m_r1 - mx1);
        float p[8][4];
        float sum0 = 0.f, sum1 = 0.f;
#pragma unroll
        for (int nt = 0; nt < 8; nt++) {
            p[nt][0] = exp2f(s[nt][0] - mx0);
            p[nt][1] = exp2f(s[nt][1] - mx0);
            p[nt][2] = exp2f(s[nt][2] - mx1);
            p[nt][3] = exp2f(s[nt][3] - mx1);
            sum0 += p[nt][0] + p[nt][1];
            sum1 += p[nt][2] + p[nt][3];
        }
        sum0 += __shfl_xor_sync(0xffffffffu, sum0, 1);
        sum0 += __shfl_xor_sync(0xffffffffu, sum0, 2);
        sum1 += __shfl_xor_sync(0xffffffffu, sum1, 1);
        sum1 += __shfl_xor_sync(0xffffffffu, sum1, 2);
        l_r0 = l_r0 * f0 + sum0; m_r0 = mx0;
        l_r1 = l_r1 * f1 + sum1; m_r1 = mx1;

        uint32_t pa[4][4];
#pragma unroll
        for (int ks = 0; ks < 4; ks++) {
            pa[ks][0] = packh2(p[2 * ks][0],     p[2 * ks][1]);
            pa[ks][1] = packh2(p[2 * ks][2],     p[2 * ks][3]);
            pa[ks][2] = packh2(p[2 * ks + 1][0], p[2 * ks + 1][1]);
            pa[ks][3] = packh2(p[2 * ks + 1][2], p[2 * ks + 1][3]);
        }

#pragma unroll
        for (int d = 0; d < 5; d++) {
            o[d][0] *= f0; o[d][1] *= f0;
            o[d][2] *= f1; o[d][3] *= f1;
        }

#pragma unroll
        for (int d = 0; d < 5; d++) {
            int vr = d * 8 + grp;
#pragma unroll
            for (int ks = 0; ks < 4; ks++) {
                uint32_t b0 = Vs[st][vr][ks * 8 + t4];
                uint32_t b1 = Vs[st][vr][ks * 8 + 4 + t4];
                mma_f16(o[d], pa[ks], b0, b1);
            }
        }
        st = (st == 2) ? 0 : st + 1;
    }

    float inv0 = 1.f / l_r0, inv1 = 1.f / l_r1;
#pragma unroll
    for (int d = 0; d < 5; d++) {
        int c = h * DH + d * 8 + 2 * t4;
        O[(size_t)row0 * DMODEL + c]     = __float2half(o[d][0] * inv0);
        O[(size_t)row0 * DMODEL + c + 1] = __float2half(o[d][1] * inv0);
        O[(size_t)row1 * DMODEL + c]     = __float2half(o[d][2] * inv1);
        O[(size_t)row1 * DMODEL + c + 1] = __float2half(o[d][3] * inv1);
    }
}

// ---------------- host launch ----------------
extern "C" void kernel_launch(void* const* d_in, const int* in_sizes, int n_in,
                              void* d_out, int out_size) {
    const float* x      = (const float*)d_in[0];
    const float* ctx    = (const float*)d_in[1];
    const float* gn_w   = (const float*)d_in[2];
    const float* gn_b   = (const float*)d_in[3];
    const float* pin_w  = (const float*)d_in[4];
    const float* pin_b  = (const float*)d_in[5];
    const float* ln1_w  = (const float*)d_in[6];
    const float* ln1_b  = (const float*)d_in[7];
    const float* q1     = (const float*)d_in[8];
    const float* k1     = (const float*)d_in[9];
    const float* v1     = (const float*)d_in[10];
    const float* o1_w   = (const float*)d_in[11];
    const float* o1_b   = (const float*)d_in[12];
    const float* ln2_w  = (const float*)d_in[13];
    const float* ln2_b  = (const float*)d_in[14];
    const float* q2     = (const float*)d_in[15];
    const float* k2     = (const float*)d_in[16];
    const float* v2     = (const float*)d_in[17];
    const float* o2_w   = (const float*)d_in[18];
    const float* o2_b   = (const float*)d_in[19];
    const float* ln3_w  = (const float*)d_in[20];
    const float* ln3_b  = (const float*)d_in[21];
    const float* ff1_w  = (const float*)d_in[22];
    const float* ff1_b  = (const float*)d_in[23];
    const float* ff2_w  = (const float*)d_in[24];
    const float* ff2_b  = (const float*)d_in[25];
    const float* pout_w = (const float*)d_in[26];
    const float* pout_b = (const float*)d_in[27];
    float* out = (float*)d_out;

    float *bp, *h, *bff1;
    __half *x16, *ln16, *qk16, *vt16, *q216, *k216, *vt2c16, *ao16, *fa16, *hh16, *ctx16;
    __half *wpin16, *wqkv16, *wq216, *wkv216, *wo116, *wo216;
    __half *wff116, *wff216, *wpo16;
    cudaGetSymbolAddress((void**)&bp, g_bp);
    cudaGetSymbolAddress((void**)&h, g_h);
    cudaGetSymbolAddress((void**)&bff1, g_bff1);
    cudaGetSymbolAddress((void**)&x16, g_x16);
    cudaGetSymbolAddress((void**)&ln16, g_ln16);
    cudaGetSymbolAddress((void**)&qk16, g_qk16);
    cudaGetSymbolAddress((void**)&vt16, g_vt16);
    cudaGetSymbolAddress((void**)&q216, g_q216);
    cudaGetSymbolAddress((void**)&k216, g_k216);
    cudaGetSymbolAddress((void**)&vt2c16, g_vt2c16);
    cudaGetSymbolAddress((void**)&ao16, g_ao16);
    cudaGetSymbolAddress((void**)&fa16, g_fa16);
    cudaGetSymbolAddress((void**)&hh16, g_hh16);
    cudaGetSymbolAddress((void**)&ctx16, g_ctx16);
    cudaGetSymbolAddress((void**)&wpin16, g_wpin16);
    cudaGetSymbolAddress((void**)&wqkv16, g_wqkv16);
    cudaGetSymbolAddress((void**)&wq216, g_wq216);
    cudaGetSymbolAddress((void**)&wkv216, g_wkv216);
    cudaGetSymbolAddress((void**)&wo116, g_wo116);
    cudaGetSymbolAddress((void**)&wo216, g_wo216);
    cudaGetSymbolAddress((void**)&wff116, g_wff116);
    cudaGetSymbolAddress((void**)&wff216, g_wff216);
    cudaGetSymbolAddress((void**)&wpo16, g_wpo16);

    // prep: 3 launches
    gn_stats_kernel<<<32, 256>>>(x, gn_w, gn_b);
    fold_pin_kernel<<<DMODEL, 64>>>(pin_w, pin_b);
    prep_kernel<<<PREP_BLOCKS, 256>>>(x, q1, k1, v1, o1_w, q2, k2, v2, o2_w,
                                      ff1_w, ff1_b, ff2_w, pout_w, ctx);

    // pin projection
    gemm_fp16<<<dim3(64, 5), 128>>>(x16, wpin16, h, nullptr, nullptr, bp, nullptr,
        NTOK, DMODEL, DMODEL, DMODEL, 1, 0, 0, 0);

    // self-attention block: fused QKV (split epilogue)
    ln_kernel<<<NTOK / 8, 256>>>(h, ln1_w, ln1_b, ln16);
    gemm_fp16<<<dim3(64, 15), 128>>>(ln16, wqkv16, nullptr, qk16, vt16, nullptr, nullptr,
        NTOK, 3 * DMODEL, DMODEL, 2 * DMODEL, 1, 2, 2 * DMODEL, NTOK);
    attn16<<<dim3(NTOK / 128, HEADS), 256>>>(
        qk16, 2 * DMODEL, qk16 + DMODEL, 2 * DMODEL, vt16, NTOK, ao16, NTOK);
    gemm_fp16<<<dim3(64, 5), 128>>>(ao16, wo116, h, nullptr, nullptr, o1_b, h,
        NTOK, DMODEL, DMODEL, DMODEL, 1, 0, 0, 0);

    // cross-attention block
    ln_kernel<<<NTOK / 8, 256>>>(h, ln2_w, ln2_b, ln16);
    gemm_fp16<<<dim3(64, 5), 128>>>(ln16, wq216, nullptr, q216, nullptr, nullptr, nullptr,
        NTOK, DMODEL, DMODEL, DMODEL, 1, 2, DMODEL, 0);
    gemm_fp16<<<dim3(2, 10), 128>>>(ctx16, wkv216, nullptr, k216, vt2c16, nullptr, nullptr,
        CTXN, 2 * DMODEL, CTXD, DMODEL, 1, 2, DMODEL, CTXP);
    attn16<<<dim3(NTOK / 128, HEADS), 256>>>(
        q216, DMODEL, k216, DMODEL, vt2c16, CTXP, ao16, CTXN);
    gemm_fp16<<<dim3(64, 5), 128>>>(ao16, wo216, h, nullptr, nullptr, o2_b, h,
        NTOK, DMODEL, DMODEL, DMODEL, 1, 0, 0, 0);

    // GEGLU FF block
    ln_kernel<<<NTOK / 8, 256>>>(h, ln3_w, ln3_b, ln16);
    gemm_fp16<<<dim3(64, 40), 128>>>(ln16, wff116, nullptr, fa16, nullptr, bff1, nullptr,
        NTOK, 2 * FFI, DMODEL, FFI, 1, 1, 0, 0);
    gemm_fp16<<<dim3(64, 5), 128>>>(fa16, wff216, h, hh16, nullptr, ff2_b, h,
        NTOK, DMODEL, FFI, DMODEL, 1, 0, 0, 0);

    // output projection (transposed store) + input residual
    gemm_fp16<<<dim3(64, 5), 128>>>(hh16, wpo16, out, nullptr, nullptr, pout_b, x,
        NTOK, DMODEL, DMODEL, 1, NTOK, 0, 0, 0);
}

// round 16
// speedup vs baseline: 1.5150x; 1.5150x over previous
#include <cuda_runtime.h>
#include <cuda_fp16.h>
#include <math.h>
#include <stdint.h>

#define NTOK 4096
#define DMODEL 320
#define FFI 1280
#define HEADS 8
#define DH 40
#define CTXN 77
#define CTXD 768
#define CTXP 128
#define QSCALE (0.15811388300841897f * 1.4426950408889634f)  // dh^-0.5 * log2(e)

// ---------------- scratch ----------------
__device__ float g_s[DMODEL];
__device__ float g_t[DMODEL];
__device__ float g_bp[DMODEL];
__device__ float g_h[NTOK * DMODEL];
__device__ float g_bff1[2 * FFI];

// fp16 activations
__device__ __align__(16) __half g_x16[NTOK * DMODEL];
__device__ __align__(16) __half g_ln16[NTOK * DMODEL];
__device__ __align__(16) __half g_qk16[NTOK * 2 * DMODEL];
__device__ __align__(16) __half g_vt16[DMODEL * NTOK];
__device__ __align__(16) __half g_q216[NTOK * DMODEL];
__device__ __align__(16) __half g_k216[CTXN * DMODEL];
__device__ __align__(16) __half g_vt2c16[DMODEL * CTXP];
__device__ __align__(16) __half g_ao16[NTOK * DMODEL];
__device__ __align__(16) __half g_fa16[NTOK * FFI];
__device__ __align__(16) __half g_hh16[NTOK * DMODEL];
__device__ __align__(16) __half g_ctx16[CTXN * CTXD];
// fp16 weights, [N][K]
__device__ __align__(16) __half g_wpin16[DMODEL * DMODEL];
__device__ __align__(16) __half g_wqkv16[3 * DMODEL * DMODEL];  // q(scaled)|k|v
__device__ __align__(16) __half g_wq216[DMODEL * DMODEL];
__device__ __align__(16) __half g_wkv216[2 * DMODEL * CTXD];    // k2|v2
__device__ __align__(16) __half g_wo116[DMODEL * DMODEL];
__device__ __align__(16) __half g_wo216[DMODEL * DMODEL];
__device__ __align__(16) __half g_wff116[2 * FFI * DMODEL];
__device__ __align__(16) __half g_wff216[DMODEL * FFI];
__device__ __align__(16) __half g_wpo16[DMODEL * DMODEL];

// ---------------- helpers ----------------
__device__ __forceinline__ uint32_t smem_u32(const void* p) {
    return (uint32_t)__cvta_generic_to_shared(p);
}
__device__ __forceinline__ void cp16(uint32_t dst, const void* src, bool pred) {
    int sz = pred ? 16 : 0;
    asm volatile("cp.async.cg.shared.global [%0], [%1], 16, %2;" :: "r"(dst), "l"(src), "r"(sz));
}
__device__ __forceinline__ void cp_commit() { asm volatile("cp.async.commit_group;"); }
__device__ __forceinline__ void cp_wait1() { asm volatile("cp.async.wait_group 1;"); }

__device__ __forceinline__ void mma_f16(float* d, const uint32_t* a, uint32_t b0, uint32_t b1) {
    asm volatile(
        "mma.sync.aligned.m16n8k16.row.col.f32.f16.f16.f32 "
        "{%0,%1,%2,%3}, {%4,%5,%6,%7}, {%8,%9}, {%0,%1,%2,%3};"
        : "+f"(d[0]), "+f"(d[1]), "+f"(d[2]), "+f"(d[3])
        : "r"(a[0]), "r"(a[1]), "r"(a[2]), "r"(a[3]), "r"(b0), "r"(b1));
}
__device__ __forceinline__ float gelu_f(float g) {
    return 0.5f * g * (1.f + erff(g * 0.70710678118654752f));
}
__device__ __forceinline__ uint32_t packh2(float a, float b) {
    __half2 p = __floats2half2_rn(a, b);
    return *(uint32_t*)&p;
}
__device__ __forceinline__ float ex2(float x) {
    float r;
    asm("ex2.approx.f32 %0, %1;" : "=f"(r) : "f"(x));
    return r;
}

// ---------------- GroupNorm stats ----------------
__global__ void gn_stats_kernel(const float* __restrict__ x,
                                const float* __restrict__ gn_w,
                                const float* __restrict__ gn_b) {
    int g = blockIdx.x;
    int tid = threadIdx.x;
    const float* base = x + (size_t)g * 10 * 4096;
    float s = 0.f, ss = 0.f;
    for (int i = tid; i < 40960; i += 256) {
        float v = base[i];
        s += v; ss += v * v;
    }
    __shared__ float r1[256], r2[256];
    r1[tid] = s; r2[tid] = ss;
    __syncthreads();
    for (int off = 128; off > 0; off >>= 1) {
        if (tid < off) { r1[tid] += r1[tid + off]; r2[tid] += r2[tid + off]; }
        __syncthreads();
    }
    if (tid < 10) {
        float mu = r1[0] / 40960.f;
        float var = r2[0] / 40960.f - mu * mu;
        float inv = rsqrtf(var + 1e-6f);
        int c = g * 10 + tid;
        float w = gn_w[c];
        g_s[c] = inv * w;
        g_t[c] = gn_b[c] - mu * inv * w;
    }
}

__global__ void fold_pin_kernel(const float* __restrict__ pin_w,
                                const float* __restrict__ pin_b) {
    int o = blockIdx.x;
    int tid = threadIdx.x;
    float acc = 0.f;
    for (int c = tid; c < DMODEL; c += 64) {
        float w = pin_w[o * DMODEL + c];
        g_wpin16[o * DMODEL + c] = __float2half(w * g_s[c]);
        acc += w * g_t[c];
    }
    __shared__ float r[64];
    r[tid] = acc;
    __syncthreads();
    for (int off = 32; off > 0; off >>= 1) {
        if (tid < off) r[tid] += r[tid + off];
        __syncthreads();
    }
    if (tid == 0) g_bp[o] = pin_b[o] + r[0];
}

// ---------------- unified weight prep ----------------
__device__ __forceinline__ void tr_tile(const float* __restrict__ in, __half* __restrict__ out,
                                        int R, int Cc, int bx, int by, float scale) {
    __shared__ float tile[32][33];
    int tx = threadIdx.x & 31, ty = threadIdx.x >> 5;
    int c0 = bx * 32, r0 = by * 32;
#pragma unroll
    for (int i = 0; i < 4; i++) {
        int r = r0 + ty + i * 8, c = c0 + tx;
        if (r < R && c < Cc) tile[ty + i * 8][tx] = in[(size_t)r * Cc + c];
    }
    __syncthreads();
#pragma unroll
    for (int i = 0; i < 4; i++) {
        int c = c0 + ty + i * 8, r = r0 + tx;
        if (c < Cc && r < R) out[(size_t)c * R + r] = __float2half(tile[tx][ty + i * 8] * scale);
    }
}

#define PREP_BLOCKS 3728
__global__ __launch_bounds__(256) void prep_kernel(
    const float* __restrict__ x,
    const float* __restrict__ q1, const float* __restrict__ k1,
    const float* __restrict__ v1, const float* __restrict__ o1w,
    const float* __restrict__ q2, const float* __restrict__ k2,
    const float* __restrict__ v2, const float* __restrict__ o2w,
    const float* __restrict__ ff1w, const float* __restrict__ ff1b,
    const float* __restrict__ ff2w, const float* __restrict__ poutw,
    const float* __restrict__ ctx) {
    int b = blockIdx.x;
    int tid = threadIdx.x;
    if (b < 1280) { tr_tile(x, g_x16, DMODEL, NTOK, b % 128, b / 128, 1.f); return; }
    b -= 1280;
    if (b < 100) { tr_tile(q1, g_wqkv16, DMODEL, DMODEL, b % 10, b / 10, QSCALE); return; }
    b -= 100;
    if (b < 100) { tr_tile(k1, g_wqkv16 + DMODEL * DMODEL, DMODEL, DMODEL, b % 10, b / 10, 1.f); return; }
    b -= 100;
    if (b < 100) { tr_tile(v1, g_wqkv16 + 2 * DMODEL * DMODEL, DMODEL, DMODEL, b % 10, b / 10, 1.f); return; }
    b -= 100;
    if (b < 100) { tr_tile(o1w, g_wo116, DMODEL, DMODEL, b % 10, b / 10, 1.f); return; }
    b -= 100;
    if (b < 100) { tr_tile(q2, g_wq216, DMODEL, DMODEL, b % 10, b / 10, QSCALE); return; }
    b -= 100;
    if (b < 240) { tr_tile(k2, g_wkv216, CTXD, DMODEL, b % 10, b / 10, 1.f); return; }
    b -= 240;
    if (b < 240) { tr_tile(v2, g_wkv216 + DMODEL * CTXD, CTXD, DMODEL, b % 10, b / 10, 1.f); return; }
    b -= 240;
    if (b < 100) { tr_tile(o2w, g_wo216, DMODEL, DMODEL, b % 10, b / 10, 1.f); return; }
    b -= 100;
    if (b < 400) { tr_tile(ff2w, g_wff216, FFI, DMODEL, b % 10, b / 10, 1.f); return; }
    b -= 400;
    if (b < 800) {
        __shared__ float tile[32][33];
        int tx = tid & 31, ty = tid >> 5;
        int bx = b % 80, by = b / 80;
        int c0 = bx * 32, r0 = by * 32;
#pragma unroll
        for (int i = 0; i < 4; i++) {
            int k = r0 + ty + i * 8, n = c0 + tx;
            int src = (n & 1) ? (FFI + (n >> 1)) : (n >> 1);
            tile[ty + i * 8][tx] = ff1w[(size_t)k * 2 * FFI + src];
        }
        __syncthreads();
#pragma unroll
        for (int i = 0; i < 4; i++) {
            int n = c0 + ty + i * 8, k = r0 + tx;
            g_wff116[(size_t)n * DMODEL + k] = __float2half(tile[tx][ty + i * 8]);
        }
        return;
    }
    b -= 800;
    if (b < 100) {
        int i0 = b * 1024 + tid * 4;
#pragma unroll
        for (int i = 0; i < 4; i++) g_wpo16[i0 + i] = __float2half(poutw[i0 + i]);
        return;
    }
    b -= 100;
    if (b < 58) {
        int i0 = b * 1024 + tid * 4;
#pragma unroll
        for (int i = 0; i < 4; i++) {
            int idx = i0 + i;
            if (idx < CTXN * CTXD) g_ctx16[idx] = __float2half(ctx[idx]);
        }
        return;
    }
    b -= 58;
    int idx = b * 256 + tid;
    int j = idx >> 1;
    g_bff1[idx] = (idx & 1) ? ff1b[FFI + j] : ff1b[j];
}

// ---------------- fp16 tensor-core GEMM, 64x64 tile, BK=32, 3-stage ----------------
__global__ __launch_bounds__(128) void gemm_fp16(
    const __half* __restrict__ A, const __half* __restrict__ B,
    float* __restrict__ C, __half* __restrict__ Ch, __half* __restrict__ Ch2,
    const float* __restrict__ bias, const float* __restrict__ resid,
    int M, int N, int K, int Csm, int Csn, int mode, int split, int ld2) {
    __shared__ __align__(16) uint32_t As[3][64][20];
    __shared__ __align__(16) uint32_t Bs[3][64][20];
    int tid = threadIdx.x;
    int warp = tid >> 5, lane = tid & 31;
    int grp = lane >> 2, t4 = lane & 3;
    int m0 = blockIdx.x * 64, n0 = blockIdx.y * 64;
    int wm = (warp >> 1) * 32, wn = (warp & 1) * 32;

    float acc[2][4][4];
#pragma unroll
    for (int mi = 0; mi < 2; mi++)
#pragma unroll
        for (int ni = 0; ni < 4; ni++)
#pragma unroll
            for (int r = 0; r < 4; r++) acc[mi][ni][r] = 0.f;

    int r0s = tid >> 2, c0s = tid & 3;
    int r1s = (tid + 128) >> 2, c1s = tid & 3;
    bool ap0 = (m0 + r0s) < M, ap1 = (m0 + r1s) < M;
    const __half* a0 = A + (size_t)(ap0 ? (m0 + r0s) : 0) * K + c0s * 8;
    const __half* a1 = A + (size_t)(ap1 ? (m0 + r1s) : 0) * K + c1s * 8;
    const __half* b0 = B + (size_t)(n0 + r0s) * K + c0s * 8;
    const __half* b1 = B + (size_t)(n0 + r1s) * K + c1s * 8;

    auto prefetch = [&](int st, int k0) {
        cp16(smem_u32(&As[st][r0s][c0s * 4]), a0 + k0, ap0);
        cp16(smem_u32(&As[st][r1s][c1s * 4]), a1 + k0, ap1);
        cp16(smem_u32(&Bs[st][r0s][c0s * 4]), b0 + k0, true);
        cp16(smem_u32(&Bs[st][r1s][c1s * 4]), b1 + k0, true);
    };

    int nK = K >> 5;
    prefetch(0, 0);
    cp_commit();
    if (nK > 1) prefetch(1, 32);
    cp_commit();
    int st = 0;
    for (int kt = 0; kt < nK; kt++) {
        cp_wait1();
        __syncthreads();
        int pf = kt + 2;
        if (pf < nK) prefetch(pf % 3, pf << 5);
        cp_commit();
#pragma unroll
        for (int kk = 0; kk < 2; kk++) {
            uint32_t af[2][4];
#pragma unroll
            for (int mi = 0; mi < 2; mi++) {
                int rm = wm + mi * 16;
                af[mi][0] = As[st][rm + grp][kk * 8 + t4];
                af[mi][1] = As[st][rm + grp + 8][kk * 8 + t4];
                af[mi][2] = As[st][rm + grp][kk * 8 + 4 + t4];
                af[mi][3] = As[st][rm + grp + 8][kk * 8 + 4 + t4];
            }
            uint32_t bf[4][2];
#pragma unroll
            for (int ni = 0; ni < 4; ni++) {
                int cn = wn + ni * 8 + grp;
                bf[ni][0] = Bs[st][cn][kk * 8 + t4];
                bf[ni][1] = Bs[st][cn][kk * 8 + 4 + t4];
            }
#pragma unroll
            for (int mi = 0; mi < 2; mi++)
#pragma unroll
                for (int ni = 0; ni < 4; ni++)
                    mma_f16(acc[mi][ni], af[mi], bf[ni][0], bf[ni][1]);
        }
        st = (st == 2) ? 0 : st + 1;
    }
#pragma unroll
    for (int mi = 0; mi < 2; mi++) {
        int r0r = m0 + wm + mi * 16 + grp;
        int r1r = r0r + 8;
#pragma unroll
        for (int ni = 0; ni < 4; ni++) {
            int c = n0 + wn + ni * 8 + t4 * 2;
            float b0v = bias ? bias[c] : 0.f;
            float b1v = bias ? bias[c + 1] : 0.f;
            if (mode == 1) {
                int co = c >> 1;
                if (r0r < M)
                    Ch[(size_t)r0r * Csm + co] =
                        __float2half((acc[mi][ni][0] + b0v) * gelu_f(acc[mi][ni][1] + b1v));
                if (r1r < M)
                    Ch[(size_t)r1r * Csm + co] =
                        __float2half((acc[mi][ni][2] + b0v) * gelu_f(acc[mi][ni][3] + b1v));
            } else if (mode == 2) {
                if (c < split) {
                    if (r0r < M) {
                        Ch[(size_t)r0r * Csm + c]     = __float2half(acc[mi][ni][0]);
                        Ch[(size_t)r0r * Csm + c + 1] = __float2half(acc[mi][ni][1]);
                    }
                    if (r1r < M) {
                        Ch[(size_t)r1r * Csm + c]     = __float2half(acc[mi][ni][2]);
                        Ch[(size_t)r1r * Csm + c + 1] = __float2half(acc[mi][ni][3]);
                    }
                } else {
                    int ct = c - split;
                    if (r0r < M) {
                        Ch2[(size_t)ct * ld2 + r0r]       = __float2half(acc[mi][ni][0]);
                        Ch2[(size_t)(ct + 1) * ld2 + r0r] = __float2half(acc[mi][ni][1]);
                    }
                    if (r1r < M) {
                        Ch2[(size_t)ct * ld2 + r1r]       = __float2half(acc[mi][ni][2]);
                        Ch2[(size_t)(ct + 1) * ld2 + r1r] = __float2half(acc[mi][ni][3]);
                    }
                }
            } else {
                if (r0r < M) {
                    size_t o0 = (size_t)r0r * Csm + (size_t)c * Csn;
                    size_t o1 = o0 + Csn;
                    float v0 = acc[mi][ni][0] + b0v;
                    float v1 = acc[mi][ni][1] + b1v;
                    if (resid) { v0 += resid[o0]; v1 += resid[o1]; }
                    if (C) { C[o0] = v0; C[o1] = v1; }
                    if (Ch) { Ch[o0] = __float2half(v0); Ch[o1] = __float2half(v1); }
                }
                if (r1r < M) {
                    size_t o0 = (size_t)r1r * Csm + (size_t)c * Csn;
                    size_t o1 = o0 + Csn;
                    float v0 = acc[mi][ni][2] + b0v;
                    float v1 = acc[mi][ni][3] + b1v;
                    if (resid) { v0 += resid[o0]; v1 += resid[o1]; }
                    if (C) { C[o0] = v0; C[o1] = v1; }
                    if (Ch) { Ch[o0] = __float2half(v0); Ch[o1] = __float2half(v1); }
                }
            }
        }
    }
}

// ---------------- LayerNorm ----------------
__global__ __launch_bounds__(256) void ln_kernel(const float* __restrict__ in,
                                                 const float* __restrict__ w,
                                                 const float* __restrict__ b,
                                                 __half* __restrict__ out) {
    int warp = threadIdx.x >> 5, lane = threadIdx.x & 31;
    int m = blockIdx.x * 8 + warp;
    const float* row = in + (size_t)m * DMODEL;
    float vals[10];
    float s = 0.f, ss = 0.f;
#pragma unroll
    for (int i = 0; i < 10; i++) {
        float v = row[lane + i * 32];
        vals[i] = v;
        s += v; ss += v * v;
    }
#pragma unroll
    for (int off = 16; off > 0; off >>= 1) {
        s += __shfl_xor_sync(0xffffffffu, s, off);
        ss += __shfl_xor_sync(0xffffffffu, ss, off);
    }
    float mu = s / (float)DMODEL;
    float var = ss / (float)DMODEL - mu * mu;
    float rs = rsqrtf(var + 1e-5f);
#pragma unroll
    for (int i = 0; i < 10; i++) {
        int c = lane + i * 32;
        out[(size_t)m * DMODEL + c] = __float2half((vals[i] - mu) * rs * w[c] + b[c]);
    }
}

// ---------------- fp16 flash attention (R14 2-stage structure, ex2 softmax) ----------------
__global__ __launch_bounds__(256) void attn16(
    const __half* __restrict__ Q, int ldq,
    const __half* __restrict__ K, int ldk,
    const __half* __restrict__ Vt, int ldv,
    __half* __restrict__ O, int n_k) {
    __shared__ __align__(16) uint32_t Ks[2][64][20];
    __shared__ __align__(16) uint32_t Vs[2][40][36];

    int h = blockIdx.y;
    int m0 = blockIdx.x * 128;
    int tid = threadIdx.x;
    int warp = tid >> 5, lane = tid & 31;
    int grp = lane >> 2, t4 = lane & 3;
    int wm = warp * 16;
    int row0 = m0 + wm + grp, row1 = row0 + 8;

    uint32_t qf[3][4];
#pragma unroll
    for (int kt = 0; kt < 3; kt++) {
        int d0 = h * DH + kt * 16 + 2 * t4;
        qf[kt][0] = *(const uint32_t*)(Q + (size_t)row0 * ldq + d0);
        qf[kt][1] = *(const uint32_t*)(Q + (size_t)row1 * ldq + d0);
        if (kt < 2) {
            qf[kt][2] = *(const uint32_t*)(Q + (size_t)row0 * ldq + d0 + 8);
            qf[kt][3] = *(const uint32_t*)(Q + (size_t)row1 * ldq + d0 + 8);
        } else {
            qf[kt][2] = 0; qf[kt][3] = 0;
        }
    }

    float o[5][4];
#pragma unroll
    for (int d = 0; d < 5; d++)
#pragma unroll
        for (int r = 0; r < 4; r++) o[d][r] = 0.f;
    float m_r0 = -1e30f, m_r1 = -1e30f, l_r0 = 0.f, l_r1 = 0.f;

    auto prefetch = [&](int st, int kt0) {
        for (int t = tid; t < 320; t += 256) {
            int r = t / 5, ch = t - r * 5;
            bool pred = (kt0 + r) < n_k;
            const __half* src = K + (size_t)(pred ? (kt0 + r) : 0) * ldk + h * DH + ch * 8;
            cp16(smem_u32(&Ks[st][r][ch * 4]), src, pred);
        }
        if (tid < 160) {
            int r = tid >> 2, ch = tid & 3;
            const __half* src = Vt + (size_t)(h * DH + r) * ldv + kt0 + ch * 16;
            cp16(smem_u32(&Vs[st][r][ch * 8]), src, true);
            src += 8;
            cp16(smem_u32(&Vs[st][r][ch * 8 + 4]), src, true);
        }
    };

    int nT = (n_k + 63) >> 6;
    prefetch(0, 0);
    cp_commit();
    for (int it = 0; it < nT; it++) {
        if (it + 1 < nT) prefetch((it + 1) & 1, (it + 1) * 64);
        cp_commit();
        cp_wait1();
        __syncthreads();
        int st = it & 1;
        int kcount = min(64, n_k - it * 64);

        float s[8][4];
#pragma unroll
        for (int nt = 0; nt < 8; nt++)
#pragma unroll
            for (int r = 0; r < 4; r++) s[nt][r] = 0.f;
#pragma unroll
        for (int kt = 0; kt < 3; kt++) {
#pragma unroll
            for (int nt = 0; nt < 8; nt++) {
                int kr = nt * 8 + grp;
                uint32_t b0 = Ks[st][kr][kt * 8 + t4];
                uint32_t b1 = (kt < 2) ? Ks[st][kr][kt * 8 + 4 + t4] : 0u;
                mma_f16(s[nt], qf[kt], b0, b1);
            }
        }
        if (kcount < 64) {
#pragma unroll
            for (int nt = 0; nt < 8; nt++) {
                int c0 = nt * 8 + 2 * t4;
                if (c0 >= kcount)     { s[nt][0] = -1e30f; s[nt][2] = -1e30f; }
                if (c0 + 1 >= kcount) { s[nt][1] = -1e30f; s[nt][3] = -1e30f; }
            }
        }

        float mx0 = m_r0, mx1 = m_r1;
#pragma unroll
        for (int nt = 0; nt < 8; nt++) {
            mx0 = fmaxf(mx0, fmaxf(s[nt][0], s[nt][1]));
            mx1 = fmaxf(mx1, fmaxf(s[nt][2], s[nt][3]));
        }
        mx0 = fmaxf(mx0, __shfl_xor_sync(0xffffffffu, mx0, 1));
        mx0 = fmaxf(mx0, __shfl_xor_sync(0xffffffffu, mx0, 2));
        mx1 = fmaxf(mx1, __shfl_xor_sync(0xffffffffu, mx1, 1));
        mx1 = fmaxf(mx1, __shfl_xor_sync(0xffffffffu, mx1, 2));
        float f0 = ex2(m_r0 - mx0), f1 = ex2(m_r1 - mx1);
        float p[8][4];
        float sum0 = 0.f, sum1 = 0.f;
#pragma unroll
        for (int nt = 0; nt < 8; nt++) {
            p[nt][0] = ex2(s[nt][0] - mx0);
            p[nt][1] = ex2(s[nt][1] - mx0);
            p[nt][2] = ex2(s[nt][2] - mx1);
            p[nt][3] = ex2(s[nt][3] - mx1);
            sum0 += p[nt][0] + p[nt][1];
            sum1 += p[nt][2] + p[nt][3];
        }
        sum0 += __shfl_xor_sync(0xffffffffu, sum0, 1);
        sum0 += __shfl_xor_sync(0xffffffffu, sum0, 2);
        sum1 += __shfl_xor_sync(0xffffffffu, sum1, 1);
        sum1 += __shfl_xor_sync(0xffffffffu, sum1, 2);
        l_r0 = l_r0 * f0 + sum0; m_r0 = mx0;
        l_r1 = l_r1 * f1 + sum1; m_r1 = mx1;

        uint32_t pa[4][4];
#pragma unroll
        for (int ks = 0; ks < 4; ks++) {
            pa[ks][0] = packh2(p[2 * ks][0],     p[2 * ks][1]);
            pa[ks][1] = packh2(p[2 * ks][2],     p[2 * ks][3]);
            pa[ks][2] = packh2(p[2 * ks + 1][0], p[2 * ks + 1][1]);
            pa[ks][3] = packh2(p[2 * ks + 1][2], p[2 * ks + 1][3]);
        }

#pragma unroll
        for (int d = 0; d < 5; d++) {
            o[d][0] *= f0; o[d][1] *= f0;
            o[d][2] *= f1; o[d][3] *= f1;
        }

#pragma unroll
        for (int d = 0; d < 5; d++) {
            int vr = d * 8 + grp;
#pragma unroll
            for (int ks = 0; ks < 4; ks++) {
                uint32_t b0 = Vs[st][vr][ks * 8 + t4];
                uint32_t b1 = Vs[st][vr][ks * 8 + 4 + t4];
                mma_f16(o[d], pa[ks], b0, b1);
            }
        }
        __syncthreads();
    }

    float inv0 = 1.f / l_r0, inv1 = 1.f / l_r1;
#pragma unroll
    for (int d = 0; d < 5; d++) {
        int c = h * DH + d * 8 + 2 * t4;
        O[(size_t)row0 * DMODEL + c]     = __float2half(o[d][0] * inv0);
        O[(size_t)row0 * DMODEL + c + 1] = __float2half(o[d][1] * inv0);
        O[(size_t)row1 * DMODEL + c]     = __float2half(o[d][2] * inv1);
        O[(size_t)row1 * DMODEL + c + 1] = __float2half(o[d][3] * inv1);
    }
}

// ---------------- host launch ----------------
extern "C" void kernel_launch(void* const* d_in, const int* in_sizes, int n_in,
                              void* d_out, int out_size) {
    const float* x      = (const float*)d_in[0];
    const float* ctx    = (const float*)d_in[1];
    const float* gn_w   = (const float*)d_in[2];
    const float* gn_b   = (const float*)d_in[3];
    const float* pin_w  = (const float*)d_in[4];
    const float* pin_b  = (const float*)d_in[5];
    const float* ln1_w  = (const float*)d_in[6];
    const float* ln1_b  = (const float*)d_in[7];
    const float* q1     = (const float*)d_in[8];
    const float* k1     = (const float*)d_in[9];
    const float* v1     = (const float*)d_in[10];
    const float* o1_w   = (const float*)d_in[11];
    const float* o1_b   = (const float*)d_in[12];
    const float* ln2_w  = (const float*)d_in[13];
    const float* ln2_b  = (const float*)d_in[14];
    const float* q2     = (const float*)d_in[15];
    const float* k2     = (const float*)d_in[16];
    const float* v2     = (const float*)d_in[17];
    const float* o2_w   = (const float*)d_in[18];
    const float* o2_b   = (const float*)d_in[19];
    const float* ln3_w  = (const float*)d_in[20];
    const float* ln3_b  = (const float*)d_in[21];
    const float* ff1_w  = (const float*)d_in[22];
    const float* ff1_b  = (const float*)d_in[23];
    const float* ff2_w  = (const float*)d_in[24];
    const float* ff2_b  = (const float*)d_in[25];
    const float* pout_w = (const float*)d_in[26];
    const float* pout_b = (const float*)d_in[27];
    float* out = (float*)d_out;

    float *bp, *h, *bff1;
    __half *x16, *ln16, *qk16, *vt16, *q216, *k216, *vt2c16, *ao16, *fa16, *hh16, *ctx16;
    __half *wpin16, *wqkv16, *wq216, *wkv216, *wo116, *wo216;
    __half *wff116, *wff216, *wpo16;
    cudaGetSymbolAddress((void**)&bp, g_bp);
    cudaGetSymbolAddress((void**)&h, g_h);
    cudaGetSymbolAddress((void**)&bff1, g_bff1);
    cudaGetSymbolAddress((void**)&x16, g_x16);
    cudaGetSymbolAddress((void**)&ln16, g_ln16);
    cudaGetSymbolAddress((void**)&qk16, g_qk16);
    cudaGetSymbolAddress((void**)&vt16, g_vt16);
    cudaGetSymbolAddress((void**)&q216, g_q216);
    cudaGetSymbolAddress((void**)&k216, g_k216);
    cudaGetSymbolAddress((void**)&vt2c16, g_vt2c16);
    cudaGetSymbolAddress((void**)&ao16, g_ao16);
    cudaGetSymbolAddress((void**)&fa16, g_fa16);
    cudaGetSymbolAddress((void**)&hh16, g_hh16);
    cudaGetSymbolAddress((void**)&ctx16, g_ctx16);
    cudaGetSymbolAddress((void**)&wpin16, g_wpin16);
    cudaGetSymbolAddress((void**)&wqkv16, g_wqkv16);
    cudaGetSymbolAddress((void**)&wq216, g_wq216);
    cudaGetSymbolAddress((void**)&wkv216, g_wkv216);
    cudaGetSymbolAddress((void**)&wo116, g_wo116);
    cudaGetSymbolAddress((void**)&wo216, g_wo216);
    cudaGetSymbolAddress((void**)&wff116, g_wff116);
    cudaGetSymbolAddress((void**)&wff216, g_wff216);
    cudaGetSymbolAddress((void**)&wpo16, g_wpo16);

    // prep: 3 launches
    gn_stats_kernel<<<32, 256>>>(x, gn_w, gn_b);
    fold_pin_kernel<<<DMODEL, 64>>>(pin_w, pin_b);
    prep_kernel<<<PREP_BLOCKS, 256>>>(x, q1, k1, v1, o1_w, q2, k2, v2, o2_w,
                                      ff1_w, ff1_b, ff2_w, pout_w, ctx);

    // pin projection
    gemm_fp16<<<dim3(64, 5), 128>>>(x16, wpin16, h, nullptr, nullptr, bp, nullptr,
        NTOK, DMODEL, DMODEL, DMODEL, 1, 0, 0, 0);

    // self-attention block: fused QKV (split epilogue)
    ln_kernel<<<NTOK / 8, 256>>>(h, ln1_w, ln1_b, ln16);
    gemm_fp16<<<dim3(64, 15), 128>>>(ln16, wqkv16, nullptr, qk16, vt16, nullptr, nullptr,
        NTOK, 3 * DMODEL, DMODEL, 2 * DMODEL, 1, 2, 2 * DMODEL, NTOK);
    attn16<<<dim3(NTOK / 128, HEADS), 256>>>(
        qk16, 2 * DMODEL, qk16 + DMODEL, 2 * DMODEL, vt16, NTOK, ao16, NTOK);
    gemm_fp16<<<dim3(64, 5), 128>>>(ao16, wo116, h, nullptr, nullptr, o1_b, h,
        NTOK, DMODEL, DMODEL, DMODEL, 1, 0, 0, 0);

    // cross-attention block
    ln_kernel<<<NTOK / 8, 256>>>(h, ln2_w, ln2_b, ln16);
    gemm_fp16<<<dim3(64, 5), 128>>>(ln16, wq216, nullptr, q216, nullptr, nullptr, nullptr,
        NTOK, DMODEL, DMODEL, DMODEL, 1, 2, DMODEL, 0);
    gemm_fp16<<<dim3(2, 10), 128>>>(ctx16, wkv216, nullptr, k216, vt2c16, nullptr, nullptr,
        CTXN, 2 * DMODEL, CTXD, DMODEL, 1, 2, DMODEL, CTXP);
    attn16<<<dim3(NTOK / 128, HEADS), 256>>>(
        q216, DMODEL, k216, DMODEL, vt2c16, CTXP, ao16, CTXN);
    gemm_fp16<<<dim3(64, 5), 128>>>(ao16, wo216, h, nullptr, nullptr, o2_b, h,
        NTOK, DMODEL, DMODEL, DMODEL, 1, 0, 0, 0);

    // GEGLU FF block
    ln_kernel<<<NTOK / 8, 256>>>(h, ln3_w, ln3_b, ln16);
    gemm_fp16<<<dim3(64, 40), 128>>>(ln16, wff116, nullptr, fa16, nullptr, bff1, nullptr,
        NTOK, 2 * FFI, DMODEL, FFI, 1, 1, 0, 0);
    gemm_fp16<<<dim3(64, 5), 128>>>(fa16, wff216, h, hh16, nullptr, ff2_b, h,
        NTOK, DMODEL, FFI, DMODEL, 1, 0, 0, 0);

    // output projection (transposed store) + input residual
    gemm_fp16<<<dim3(64, 5), 128>>>(hh16, wpo16, out, nullptr, nullptr, pout_b, x,
        NTOK, DMODEL, DMODEL, 1, NTOK, 0, 0, 0);
}